// round 3
// baseline (speedup 1.0000x reference)
#include <cuda_runtime.h>
#include <cuda_bf16.h>
#include <math_constants.h>

// Problem constants
#define Bz     4
#define C_IN   192
#define Nn     4096
#define BN     (Bz * Nn)          // 16384 nodes
#define E_CNT  262144             // edges
#define C_OUT  384
#define K2     (2 * C_IN)         // 384

// ---------------- scratch (static device globals; no allocation) ----------------
__device__ float g_xt[BN * C_IN];        // node-major copy of x   (12.6 MB)
__device__ float g_agg[BN * C_IN];       // node-major aggregation (12.6 MB)
__device__ float g_wx[C_OUT * C_IN];     // W[:, 0::2]
__device__ float g_wg[C_OUT * C_IN];     // W[:, 1::2]
__device__ int   g_cnt[BN];
__device__ int   g_offs[BN + 1];
__device__ int   g_cursor[BN];
__device__ int   g_bucket[E_CNT];
__device__ int   g_is64;                 // edge dtype flag (1 = int64, 0 = int32)

// ---------------- edge dtype probe (device-side, capturable, deterministic) ----
// JAX with x64 disabled silently downcasts jnp.int64 -> int32. Detect which
// layout the harness actually gave us: interpret the first 256 entries as
// int64; any value outside [0, BN) proves the buffer is int32.
__global__ void probe_kernel(const void* __restrict__ ei) {
    if (threadIdx.x == 0 && blockIdx.x == 0) g_is64 = 1;
    __threadfence();
    const long long* p = (const long long*)ei;
    int i = threadIdx.x;             // 256 threads
    long long v = p[i];
    if (v < 0 || v >= BN) atomicExch(&g_is64, 0);
}

__device__ __forceinline__ int load_edge(const void* ei, int idx) {
    if (g_is64) return (int)((const long long*)ei)[idx];
    return ((const int*)ei)[idx];
}

// ---------------- tiny prep kernels ----------------
__global__ void zero_counts_kernel() {
    int i = blockIdx.x * blockDim.x + threadIdx.x;
    if (i < BN) g_cnt[i] = 0;
}

__global__ void wprep_kernel(const float* __restrict__ W) {
    int i = blockIdx.x * blockDim.x + threadIdx.x;   // over C_OUT*C_IN
    if (i < C_OUT * C_IN) {
        int o = i / C_IN, c = i % C_IN;
        g_wx[i] = W[o * K2 + 2 * c];
        g_wg[i] = W[o * K2 + 2 * c + 1];
    }
}

// x (B, C, N) -> x_t (B*N, C) node-major, via 32x32 shared tiles
__global__ void transpose_kernel(const float* __restrict__ x) {
    __shared__ float tile[32][33];
    int b  = blockIdx.z;
    int n0 = blockIdx.x * 32;
    int c0 = blockIdx.y * 32;
    int tx = threadIdx.x, ty = threadIdx.y;   // 32 x 8
    #pragma unroll
    for (int i = 0; i < 4; ++i) {
        int c = c0 + ty + 8 * i;
        tile[ty + 8 * i][tx] = x[((size_t)b * C_IN + c) * Nn + n0 + tx];
    }
    __syncthreads();
    #pragma unroll
    for (int i = 0; i < 4; ++i) {
        int n = n0 + ty + 8 * i;
        g_xt[((size_t)b * Nn + n) * C_IN + c0 + tx] = tile[tx][ty + 8 * i];
    }
}

// ---------------- CSR bucketing of edges by dst ----------------
__global__ void hist_kernel(const void* __restrict__ ei) {
    int e = blockIdx.x * blockDim.x + threadIdx.x;
    if (e < E_CNT) {
        int d = load_edge(ei, e);               // row 0 = dst
        if ((unsigned)d < BN) atomicAdd(&g_cnt[d], 1);
    }
}

// single-block scan over BN=16384 counters (1024 threads x 16 each)
__global__ void scan_kernel() {
    __shared__ int sh[1024];
    int t = threadIdx.x;
    int local[16];
    int sum = 0;
    #pragma unroll
    for (int j = 0; j < 16; ++j) {
        local[j] = g_cnt[t * 16 + j];
        sum += local[j];
    }
    sh[t] = sum;
    __syncthreads();
    for (int off = 1; off < 1024; off <<= 1) {
        int v = (t >= off) ? sh[t - off] : 0;
        __syncthreads();
        sh[t] += v;
        __syncthreads();
    }
    int run = sh[t] - sum;                // exclusive base
    #pragma unroll
    for (int j = 0; j < 16; ++j) {
        g_offs[t * 16 + j]   = run;
        g_cursor[t * 16 + j] = run;
        run += local[j];
    }
    if (t == 1023) g_offs[BN] = run;      // <= E_CNT
}

__global__ void scatter_kernel(const void* __restrict__ ei) {
    int e = blockIdx.x * blockDim.x + threadIdx.x;
    if (e < E_CNT) {
        int d = load_edge(ei, e);
        int s = load_edge(ei, E_CNT + e);       // row 1 = src
        if ((unsigned)d < BN && (unsigned)s < BN) {
            int pos = atomicAdd(&g_cursor[d], 1);
            if (pos < E_CNT) g_bucket[pos] = s;
        }
    }
}

// ---------------- aggregation: one warp per node ----------------
// agg[i][c] = (deg>0) ? max_src(x_t[src][c]) - x_t[i][c] : 0
__global__ void agg_kernel() {
    int gtid = blockIdx.x * blockDim.x + threadIdx.x;
    int node = gtid >> 5;
    int lane = threadIdx.x & 31;
    if (node >= BN) return;
    int start = g_offs[node];
    int end   = g_offs[node + 1];
    float m[6];
    #pragma unroll
    for (int j = 0; j < 6; ++j) m[j] = -CUDART_INF_F;
    for (int e = start; e < end; ++e) {
        int s = g_bucket[e];
        const float* xs = g_xt + (size_t)s * C_IN;
        #pragma unroll
        for (int j = 0; j < 6; ++j)
            m[j] = fmaxf(m[j], xs[lane + 32 * j]);
    }
    const float* xi = g_xt + (size_t)node * C_IN;
    float* ag       = g_agg + (size_t)node * C_IN;
    bool has = end > start;
    #pragma unroll
    for (int j = 0; j < 6; ++j)
        ag[lane + 32 * j] = has ? (m[j] - xi[lane + 32 * j]) : 0.0f;
}

// ---------------- fused dual-GEMM + bias + ReLU ----------------
// out_b(384 x 4096) = relu( Wx @ x_b + Wg @ agg_b^T + bias )
#define TM 128
#define TN 128
#define KB 16

__global__ __launch_bounds__(256) void gemm_kernel(
    const float* __restrict__ x,
    const float* __restrict__ bias,
    float* __restrict__ out)
{
    __shared__ float a_s[KB][TM + 4];
    __shared__ float b_s[KB][TN + 4];

    int n0 = blockIdx.x * TN;
    int m0 = blockIdx.y * TM;
    int b  = blockIdx.z;
    int tid = threadIdx.x;
    int tx = tid % 16, ty = tid / 16;

    const float* xb   = x     + (size_t)b * C_IN * Nn;   // (C, N)
    const float* aggb = g_agg + (size_t)b * Nn * C_IN;   // (N, C)

    float acc[8][8];
    #pragma unroll
    for (int i = 0; i < 8; ++i)
        #pragma unroll
        for (int j = 0; j < 8; ++j) acc[i][j] = 0.0f;

    #pragma unroll
    for (int src = 0; src < 2; ++src) {
        const float* Wm = src == 0 ? g_wx : g_wg;
        for (int k0 = 0; k0 < C_IN; k0 += KB) {
            // A tile: a_s[k][m] = Wm[(m0+m)*C_IN + k0+k]
            #pragma unroll
            for (int i = 0; i < 8; ++i) {
                int idx = tid + 256 * i;      // 0..2047
                int k = idx % KB;
                int m = idx / KB;
                a_s[k][m] = Wm[(size_t)(m0 + m) * C_IN + k0 + k];
            }
            // B tile
            if (src == 0) {
                #pragma unroll
                for (int i = 0; i < 8; ++i) {
                    int idx = tid + 256 * i;
                    int k = idx / TN;
                    int n = idx % TN;
                    b_s[k][n] = xb[(size_t)(k0 + k) * Nn + n0 + n];
                }
            } else {
                #pragma unroll
                for (int i = 0; i < 8; ++i) {
                    int idx = tid + 256 * i;
                    int k = idx % KB;
                    int n = idx / KB;
                    b_s[k][n] = aggb[(size_t)(n0 + n) * C_IN + k0 + k];
                }
            }
            __syncthreads();
            #pragma unroll
            for (int k = 0; k < KB; ++k) {
                float a[8], bb[8];
                #pragma unroll
                for (int i = 0; i < 8; ++i) a[i]  = a_s[k][ty * 8 + i];
                #pragma unroll
                for (int j = 0; j < 8; ++j) bb[j] = b_s[k][tx * 8 + j];
                #pragma unroll
                for (int i = 0; i < 8; ++i)
                    #pragma unroll
                    for (int j = 0; j < 8; ++j)
                        acc[i][j] = fmaf(a[i], bb[j], acc[i][j]);
            }
            __syncthreads();
        }
    }

    // epilogue: bias + relu, coalesced along n
    #pragma unroll
    for (int i = 0; i < 8; ++i) {
        int o = m0 + ty * 8 + i;
        float bv = bias[o];
        float* orow = out + ((size_t)b * C_OUT + o) * Nn + n0;
        #pragma unroll
        for (int j = 0; j < 8; ++j) {
            float v = acc[i][j] + bv;
            orow[tx * 8 + j] = v > 0.0f ? v : 0.0f;
        }
    }
}

// ---------------- launcher ----------------
extern "C" void kernel_launch(void* const* d_in, const int* in_sizes, int n_in,
                              void* d_out, int out_size) {
    const float* x  = (const float*)d_in[0];       // (4,192,4096,1)
    const void*  ei = (const void*)d_in[1];        // (2, 262144) int32 or int64
    const float* W  = (const float*)d_in[2];       // (384, 384)
    const float* bv = (const float*)d_in[3];       // (384,)
    float* out = (float*)d_out;                    // (4,384,4096,1)

    probe_kernel<<<1, 256>>>(ei);
    zero_counts_kernel<<<BN / 256, 256>>>();
    wprep_kernel<<<(C_OUT * C_IN + 255) / 256, 256>>>(W);
    transpose_kernel<<<dim3(Nn / 32, C_IN / 32, Bz), dim3(32, 8)>>>(x);
    hist_kernel<<<E_CNT / 256, 256>>>(ei);
    scan_kernel<<<1, 1024>>>();
    scatter_kernel<<<E_CNT / 256, 256>>>(ei);
    agg_kernel<<<(BN * 32) / 256, 256>>>();
    gemm_kernel<<<dim3(Nn / TN, C_OUT / TM, Bz), 256>>>(x, bv, out);
}

// round 5
// speedup vs baseline: 1.8841x; 1.8841x over previous
#include <cuda_runtime.h>
#include <cuda_bf16.h>
#include <math_constants.h>
#include <cstdint>

// Problem constants
#define Bz     4
#define C_IN   192
#define Nn     4096
#define BN     (Bz * Nn)          // 16384 nodes
#define E_CNT  262144             // edges
#define C_OUT  384
#define K2     (2 * C_IN)         // 384  (combined GEMM K)

// ---------------- scratch (static device globals; no allocation) ----------------
__device__ float g_xt[BN * C_IN];                           // node-major fp32 x (agg gather)
__device__ __align__(16) __nv_bfloat16 g_bx_hi[BN * C_IN];  // x  node-major bf16 hi
__device__ __align__(16) __nv_bfloat16 g_bx_lo[BN * C_IN];  // x  node-major bf16 lo
__device__ __align__(16) __nv_bfloat16 g_bg_hi[BN * C_IN];  // agg node-major bf16 hi
__device__ __align__(16) __nv_bfloat16 g_bg_lo[BN * C_IN];  // agg node-major bf16 lo
__device__ __align__(16) __nv_bfloat16 g_a_hi[C_OUT * K2];  // A=[Wx|Wg] K-major bf16 hi
__device__ __align__(16) __nv_bfloat16 g_a_lo[C_OUT * K2];  // A lo
__device__ int   g_cnt[BN];
__device__ int   g_offs[BN + 1];
__device__ int   g_cursor[BN];
__device__ int   g_bucket[E_CNT];
__device__ int   g_is64;                 // edge dtype flag (1 = int64, 0 = int32)

// ---------------- helpers ----------------
__device__ __forceinline__ uint32_t smem_u32(const void* p) {
    uint32_t a;
    asm("{ .reg .u64 t; cvta.to.shared.u64 t, %1; cvt.u32.u64 %0, t; }" : "=r"(a) : "l"(p));
    return a;
}

__device__ __forceinline__ void ldsm_x4(uint32_t addr, uint32_t& r0, uint32_t& r1,
                                        uint32_t& r2, uint32_t& r3) {
    asm volatile("ldmatrix.sync.aligned.m8n8.x4.shared.b16 {%0,%1,%2,%3}, [%4];"
                 : "=r"(r0), "=r"(r1), "=r"(r2), "=r"(r3) : "r"(addr));
}

__device__ __forceinline__ void mma_bf16(float& c0, float& c1, float& c2, float& c3,
                                         uint32_t a0, uint32_t a1, uint32_t a2, uint32_t a3,
                                         uint32_t b0, uint32_t b1) {
    asm volatile(
        "mma.sync.aligned.m16n8k16.row.col.f32.bf16.bf16.f32 "
        "{%0,%1,%2,%3}, {%4,%5,%6,%7}, {%8,%9}, {%0,%1,%2,%3};"
        : "+f"(c0), "+f"(c1), "+f"(c2), "+f"(c3)
        : "r"(a0), "r"(a1), "r"(a2), "r"(a3), "r"(b0), "r"(b1));
}

// ---------------- edge dtype probe ----------------
__global__ void probe_kernel(const void* __restrict__ ei) {
    if (threadIdx.x == 0 && blockIdx.x == 0) g_is64 = 1;
    __threadfence();
    const long long* p = (const long long*)ei;
    long long v = p[threadIdx.x];
    if (v < 0 || v >= BN) atomicExch(&g_is64, 0);
}
__device__ __forceinline__ int load_edge(const void* ei, int idx) {
    if (g_is64) return (int)((const long long*)ei)[idx];
    return ((const int*)ei)[idx];
}

// ---------------- prep ----------------
__global__ void zero_counts_kernel() {
    int i = blockIdx.x * blockDim.x + threadIdx.x;
    if (i < BN) g_cnt[i] = 0;
}

__device__ __forceinline__ void split_bf16(float v, __nv_bfloat16& hi, __nv_bfloat16& lo) {
    hi = __float2bfloat16(v);
    lo = __float2bfloat16(v - __bfloat162float(hi));
}

// Build combined A = [Wx | Wg] in K-major bf16 hi/lo
__global__ void wprep_kernel(const float* __restrict__ W) {
    int i = blockIdx.x * blockDim.x + threadIdx.x;     // over C_OUT*K2
    if (i < C_OUT * K2) {
        int o = i / K2, k = i % K2;
        float v = (k < C_IN) ? W[o * K2 + 2 * k] : W[o * K2 + 2 * (k - C_IN) + 1];
        __nv_bfloat16 hi, lo;
        split_bf16(v, hi, lo);
        g_a_hi[i] = hi;
        g_a_lo[i] = lo;
    }
}

// x (B, C, N) -> node-major fp32 + bf16 hi/lo
__global__ void transpose_kernel(const float* __restrict__ x) {
    __shared__ float tile[32][33];
    int b  = blockIdx.z;
    int n0 = blockIdx.x * 32;
    int c0 = blockIdx.y * 32;
    int tx = threadIdx.x, ty = threadIdx.y;   // 32 x 8
    #pragma unroll
    for (int i = 0; i < 4; ++i) {
        int c = c0 + ty + 8 * i;
        tile[ty + 8 * i][tx] = x[((size_t)b * C_IN + c) * Nn + n0 + tx];
    }
    __syncthreads();
    #pragma unroll
    for (int i = 0; i < 4; ++i) {
        int n = n0 + ty + 8 * i;
        size_t idx = ((size_t)b * Nn + n) * C_IN + c0 + tx;
        float v = tile[tx][ty + 8 * i];
        g_xt[idx] = v;
        __nv_bfloat16 hi, lo;
        split_bf16(v, hi, lo);
        g_bx_hi[idx] = hi;
        g_bx_lo[idx] = lo;
    }
}

// ---------------- CSR bucketing ----------------
__global__ void hist_kernel(const void* __restrict__ ei) {
    int e = blockIdx.x * blockDim.x + threadIdx.x;
    if (e < E_CNT) {
        int d = load_edge(ei, e);
        if ((unsigned)d < BN) atomicAdd(&g_cnt[d], 1);
    }
}

__global__ void scan_kernel() {
    __shared__ int sh[1024];
    int t = threadIdx.x;
    int local[16];
    int sum = 0;
    #pragma unroll
    for (int j = 0; j < 16; ++j) {
        local[j] = g_cnt[t * 16 + j];
        sum += local[j];
    }
    sh[t] = sum;
    __syncthreads();
    for (int off = 1; off < 1024; off <<= 1) {
        int v = (t >= off) ? sh[t - off] : 0;
        __syncthreads();
        sh[t] += v;
        __syncthreads();
    }
    int run = sh[t] - sum;
    #pragma unroll
    for (int j = 0; j < 16; ++j) {
        g_offs[t * 16 + j]   = run;
        g_cursor[t * 16 + j] = run;
        run += local[j];
    }
    if (t == 1023) g_offs[BN] = run;
}

__global__ void scatter_kernel(const void* __restrict__ ei) {
    int e = blockIdx.x * blockDim.x + threadIdx.x;
    if (e < E_CNT) {
        int d = load_edge(ei, e);
        int s = load_edge(ei, E_CNT + e);
        if ((unsigned)d < BN && (unsigned)s < BN) {
            int pos = atomicAdd(&g_cursor[d], 1);
            if (pos < E_CNT) g_bucket[pos] = s;
        }
    }
}

// ---------------- aggregation: one warp per node ----------------
__global__ void agg_kernel() {
    int gtid = blockIdx.x * blockDim.x + threadIdx.x;
    int node = gtid >> 5;
    int lane = threadIdx.x & 31;
    if (node >= BN) return;
    int start = g_offs[node];
    int end   = g_offs[node + 1];
    float m[6];
    #pragma unroll
    for (int j = 0; j < 6; ++j) m[j] = -CUDART_INF_F;
    for (int e = start; e < end; ++e) {
        int s = g_bucket[e];
        const float* xs = g_xt + (size_t)s * C_IN;
        #pragma unroll
        for (int j = 0; j < 6; ++j)
            m[j] = fmaxf(m[j], xs[lane + 32 * j]);
    }
    const float* xi = g_xt + (size_t)node * C_IN;
    bool has = end > start;
    #pragma unroll
    for (int j = 0; j < 6; ++j) {
        float v = has ? (m[j] - xi[lane + 32 * j]) : 0.0f;
        __nv_bfloat16 hi, lo;
        split_bf16(v, hi, lo);
        size_t idx = (size_t)node * C_IN + lane + 32 * j;
        g_bg_hi[idx] = hi;
        g_bg_lo[idx] = lo;
    }
}

// ---------------- HMMA GEMM: out = relu(A @ B + bias) ----------------
// A (384 x 384) bf16 hi/lo, K-major rows. B per batch (4096 x 384 K-major):
// K rows 0..191 from x, 192..383 from agg. 3-term bf16 split:
//   D = A_hi*B_hi + A_hi*B_lo + A_lo*B_hi   (fp32 accum in registers)
// CTA tile 128(M) x 128(N); 8 warps = 4(M) x 2(N), warp tile 32 x 64.
// K chunks of 64 bf16; 18 chunks = 3 terms x 6.
// smem tiles: 128 rows x 64 bf16, row pitch 144B (bank-conflict-free ldmatrix).

#define PITCH_B 144
#define PITCH_E 72      // pitch in bf16 elements

__global__ __launch_bounds__(256, 2) void hmma_gemm_kernel(
    const float* __restrict__ bias, float* __restrict__ out)
{
    __shared__ __align__(16) __nv_bfloat16 As[128 * PITCH_E];   // 18 KB
    __shared__ __align__(16) __nv_bfloat16 Bs[128 * PITCH_E];   // 18 KB

    int tid  = threadIdx.x;
    int wid  = tid >> 5;
    int lane = tid & 31;
    int wm   = wid & 3;        // warp row 0..3  -> m offset wm*32
    int wn   = wid >> 2;       // warp col 0..1  -> n offset wn*64
    int n0 = blockIdx.x * 128;
    int m0 = blockIdx.y * 128;
    int bb = blockIdx.z;

    uint32_t as_base = smem_u32(As);
    uint32_t bs_base = smem_u32(Bs);

    // ldmatrix lane address components
    int row_in = lane & 7;
    int sub    = lane >> 3;      // 0..3

    // A frag address: row = mBase + row_in + (sub&1)*8 ; col = k0 + (sub>>1)*8
    // B frag address: row(n) = nBase + (sub>>1)*8 + row_in ; col = k0 + (sub&1)*8

    const char* bx_hi = (const char*)g_bx_hi;
    const char* bx_lo = (const char*)g_bx_lo;
    const char* bg_hi = (const char*)g_bg_hi;
    const char* bg_lo = (const char*)g_bg_lo;
    const char* a_hi  = (const char*)g_a_hi;
    const char* a_lo  = (const char*)g_a_lo;

    int node0 = bb * Nn + n0;

    float acc[2][8][4];
    #pragma unroll
    for (int i = 0; i < 2; ++i)
        #pragma unroll
        for (int j = 0; j < 8; ++j)
            #pragma unroll
            for (int r = 0; r < 4; ++r) acc[i][j][r] = 0.0f;

    for (int t = 0; t < 18; ++t) {
        int term = t / 6;          // 0: hi*hi, 1: hi*lo, 2: lo*hi
        int c6   = t - term * 6;   // K-chunk 0..5 within 384-K pass
        const char* asrc = (term < 2) ? a_hi : a_lo;
        const char* bsrc;
        if (c6 < 3) bsrc = (term == 1) ? bx_lo : bx_hi;
        else        bsrc = (term == 1) ? bg_lo : bg_hi;
        int kkA = c6 * 64;                 // A K-offset (bf16 elements)
        int kkB = (c6 % 3) * 64;           // B K-offset within its source

        // fill tiles: 128 rows x 8 granules(16B) each = 1024 granule writes
        #pragma unroll
        for (int i = 0; i < 4; ++i) {
            int idx = tid + 256 * i;       // 0..1023
            int row = idx >> 3;
            int q   = idx & 7;
            uint4 va = *(const uint4*)(asrc + (size_t)(m0 + row) * (K2 * 2) + kkA * 2 + q * 16);
            *(uint4*)((char*)As + row * PITCH_B + q * 16) = va;
            uint4 vb = *(const uint4*)(bsrc + (size_t)(node0 + row) * (C_IN * 2) + kkB * 2 + q * 16);
            *(uint4*)((char*)Bs + row * PITCH_B + q * 16) = vb;
        }
        __syncthreads();

        #pragma unroll
        for (int ks = 0; ks < 4; ++ks) {
            int k0 = ks * 16;
            // A fragments (2 x m16)
            uint32_t a[2][4];
            #pragma unroll
            for (int f = 0; f < 2; ++f) {
                int row = wm * 32 + f * 16 + row_in + (sub & 1) * 8;
                uint32_t addr = as_base + row * PITCH_B + (k0 + (sub >> 1) * 8) * 2;
                ldsm_x4(addr, a[f][0], a[f][1], a[f][2], a[f][3]);
            }
            // B fragments (8 x n8) via 4 x ldmatrix.x4
            uint32_t b[8][2];
            #pragma unroll
            for (int j = 0; j < 4; ++j) {
                int nrow = wn * 64 + j * 16 + (sub >> 1) * 8 + row_in;
                uint32_t addr = bs_base + nrow * PITCH_B + (k0 + (sub & 1) * 8) * 2;
                uint32_t r0, r1, r2, r3;
                ldsm_x4(addr, r0, r1, r2, r3);
                b[j * 2][0]     = r0; b[j * 2][1]     = r1;
                b[j * 2 + 1][0] = r2; b[j * 2 + 1][1] = r3;
            }
            #pragma unroll
            for (int mi = 0; mi < 2; ++mi)
                #pragma unroll
                for (int nj = 0; nj < 8; ++nj)
                    mma_bf16(acc[mi][nj][0], acc[mi][nj][1], acc[mi][nj][2], acc[mi][nj][3],
                             a[mi][0], a[mi][1], a[mi][2], a[mi][3],
                             b[nj][0], b[nj][1]);
        }
        __syncthreads();
    }

    // epilogue: bias + relu
    int g  = lane >> 2;        // 0..7
    int tq = lane & 3;         // 0..3
    #pragma unroll
    for (int mi = 0; mi < 2; ++mi) {
        int r0 = m0 + wm * 32 + mi * 16 + g;
        int r1 = r0 + 8;
        float bv0 = bias[r0];
        float bv1 = bias[r1];
        float* o0 = out + ((size_t)bb * C_OUT + r0) * Nn + n0 + wn * 64 + tq * 2;
        float* o1 = out + ((size_t)bb * C_OUT + r1) * Nn + n0 + wn * 64 + tq * 2;
        #pragma unroll
        for (int nj = 0; nj < 8; ++nj) {
            float2 v0, v1;
            v0.x = fmaxf(acc[mi][nj][0] + bv0, 0.0f);
            v0.y = fmaxf(acc[mi][nj][1] + bv0, 0.0f);
            v1.x = fmaxf(acc[mi][nj][2] + bv1, 0.0f);
            v1.y = fmaxf(acc[mi][nj][3] + bv1, 0.0f);
            *(float2*)(o0 + nj * 8) = v0;
            *(float2*)(o1 + nj * 8) = v1;
        }
    }
}

// ---------------- launcher ----------------
extern "C" void kernel_launch(void* const* d_in, const int* in_sizes, int n_in,
                              void* d_out, int out_size) {
    const float* x  = (const float*)d_in[0];       // (4,192,4096,1)
    const void*  ei = (const void*)d_in[1];        // (2, 262144) int32 or int64
    const float* W  = (const float*)d_in[2];       // (384, 384)
    const float* bv = (const float*)d_in[3];       // (384,)
    float* out = (float*)d_out;                    // (4,384,4096,1)

    probe_kernel<<<1, 256>>>(ei);
    zero_counts_kernel<<<BN / 256, 256>>>();
    wprep_kernel<<<(C_OUT * K2 + 255) / 256, 256>>>(W);
    transpose_kernel<<<dim3(Nn / 32, C_IN / 32, Bz), dim3(32, 8)>>>(x);
    hist_kernel<<<E_CNT / 256, 256>>>(ei);
    scan_kernel<<<1, 1024>>>();
    scatter_kernel<<<E_CNT / 256, 256>>>(ei);
    agg_kernel<<<(BN * 32) / 256, 256>>>();
    hmma_gemm_kernel<<<dim3(Nn / 128, C_OUT / 128, Bz), 256>>>(bv, out);
}

// round 6
// speedup vs baseline: 2.0905x; 1.1095x over previous
#include <cuda_runtime.h>
#include <cuda_bf16.h>
#include <math_constants.h>
#include <cstdint>

// Problem constants
#define Bz     4
#define C_IN   192
#define Nn     4096
#define BN     (Bz * Nn)          // 16384 nodes
#define E_CNT  262144             // edges
#define C_OUT  384
#define K2     (2 * C_IN)         // 384  (combined GEMM K)

// ---------------- scratch (static device globals; no allocation) ----------------
__device__ float g_xt[BN * C_IN];                           // node-major fp32 x (agg gather)
__device__ __align__(16) __nv_bfloat16 g_bx_hi[BN * C_IN];  // x  node-major bf16 hi
__device__ __align__(16) __nv_bfloat16 g_bx_lo[BN * C_IN];  // x  node-major bf16 lo
__device__ __align__(16) __nv_bfloat16 g_bg_hi[BN * C_IN];  // agg node-major bf16 hi
__device__ __align__(16) __nv_bfloat16 g_bg_lo[BN * C_IN];  // agg node-major bf16 lo
__device__ __align__(16) __nv_bfloat16 g_a_hi[C_OUT * K2];  // A=[Wx|Wg] K-major bf16 hi
__device__ __align__(16) __nv_bfloat16 g_a_lo[C_OUT * K2];  // A lo
__device__ int   g_cnt[BN];
__device__ int   g_offs[BN + 1];
__device__ int   g_cursor[BN];
__device__ int   g_bucket[E_CNT];
__device__ int   g_is64;                 // edge dtype flag (1 = int64, 0 = int32)

// ---------------- helpers ----------------
__device__ __forceinline__ uint32_t smem_u32(const void* p) {
    uint32_t a;
    asm("{ .reg .u64 t; cvta.to.shared.u64 t, %1; cvt.u32.u64 %0, t; }" : "=r"(a) : "l"(p));
    return a;
}

__device__ __forceinline__ void ldsm_x4(uint32_t addr, uint32_t& r0, uint32_t& r1,
                                        uint32_t& r2, uint32_t& r3) {
    asm volatile("ldmatrix.sync.aligned.m8n8.x4.shared.b16 {%0,%1,%2,%3}, [%4];"
                 : "=r"(r0), "=r"(r1), "=r"(r2), "=r"(r3) : "r"(addr));
}

__device__ __forceinline__ void mma_bf16(float& c0, float& c1, float& c2, float& c3,
                                         uint32_t a0, uint32_t a1, uint32_t a2, uint32_t a3,
                                         uint32_t b0, uint32_t b1) {
    asm volatile(
        "mma.sync.aligned.m16n8k16.row.col.f32.bf16.bf16.f32 "
        "{%0,%1,%2,%3}, {%4,%5,%6,%7}, {%8,%9}, {%0,%1,%2,%3};"
        : "+f"(c0), "+f"(c1), "+f"(c2), "+f"(c3)
        : "r"(a0), "r"(a1), "r"(a2), "r"(a3), "r"(b0), "r"(b1));
}

__device__ __forceinline__ int load_edge(const void* ei, int idx) {
    if (g_is64) return (int)((const long long*)ei)[idx];
    return ((const int*)ei)[idx];
}

__device__ __forceinline__ void split_bf16(float v, __nv_bfloat16& hi, __nv_bfloat16& lo) {
    hi = __float2bfloat16(v);
    lo = __float2bfloat16(v - __bfloat162float(hi));
}

// ---------------- merged prep: probe + zero counts + W deinterleave/split ------
// block 0           : edge-dtype probe (256 threads read first 256 int64 slots)
// blocks 1..64      : zero g_cnt
// blocks 65..640    : build A = [Wx | Wg] bf16 hi/lo (576 blocks x 256 = C_OUT*K2)
__global__ void prep_kernel(const void* __restrict__ ei, const float* __restrict__ W) {
    int blk = blockIdx.x;
    int t   = threadIdx.x;
    if (blk == 0) {
        if (t == 0) g_is64 = 1;
        __threadfence();
        const long long* p = (const long long*)ei;
        long long v = p[t];
        if (v < 0 || v >= BN) atomicExch(&g_is64, 0);
    } else if (blk <= 64) {
        g_cnt[(blk - 1) * 256 + t] = 0;
    } else {
        int i = (blk - 65) * 256 + t;            // over C_OUT*K2
        int o = i / K2, k = i % K2;
        float v = (k < C_IN) ? W[o * K2 + 2 * k] : W[o * K2 + 2 * (k - C_IN) + 1];
        __nv_bfloat16 hi, lo;
        split_bf16(v, hi, lo);
        g_a_hi[i] = hi;
        g_a_lo[i] = lo;
    }
}

// x (B, C, N) -> node-major fp32 + bf16 hi/lo
__global__ void transpose_kernel(const float* __restrict__ x) {
    __shared__ float tile[32][33];
    int b  = blockIdx.z;
    int n0 = blockIdx.x * 32;
    int c0 = blockIdx.y * 32;
    int tx = threadIdx.x, ty = threadIdx.y;   // 32 x 8
    #pragma unroll
    for (int i = 0; i < 4; ++i) {
        int c = c0 + ty + 8 * i;
        tile[ty + 8 * i][tx] = x[((size_t)b * C_IN + c) * Nn + n0 + tx];
    }
    __syncthreads();
    #pragma unroll
    for (int i = 0; i < 4; ++i) {
        int n = n0 + ty + 8 * i;
        size_t idx = ((size_t)b * Nn + n) * C_IN + c0 + tx;
        float v = tile[tx][ty + 8 * i];
        g_xt[idx] = v;
        __nv_bfloat16 hi, lo;
        split_bf16(v, hi, lo);
        g_bx_hi[idx] = hi;
        g_bx_lo[idx] = lo;
    }
}

// ---------------- CSR bucketing ----------------
__global__ void hist_kernel(const void* __restrict__ ei) {
    int e = blockIdx.x * blockDim.x + threadIdx.x;
    if (e < E_CNT) {
        int d = load_edge(ei, e);
        if ((unsigned)d < BN) atomicAdd(&g_cnt[d], 1);
    }
}

__global__ void scan_kernel() {
    __shared__ int sh[1024];
    int t = threadIdx.x;
    int local[16];
    int sum = 0;
    #pragma unroll
    for (int j = 0; j < 16; ++j) {
        local[j] = g_cnt[t * 16 + j];
        sum += local[j];
    }
    sh[t] = sum;
    __syncthreads();
    for (int off = 1; off < 1024; off <<= 1) {
        int v = (t >= off) ? sh[t - off] : 0;
        __syncthreads();
        sh[t] += v;
        __syncthreads();
    }
    int run = sh[t] - sum;
    #pragma unroll
    for (int j = 0; j < 16; ++j) {
        g_offs[t * 16 + j]   = run;
        g_cursor[t * 16 + j] = run;
        run += local[j];
    }
    if (t == 1023) g_offs[BN] = run;
}

__global__ void scatter_kernel(const void* __restrict__ ei) {
    int e = blockIdx.x * blockDim.x + threadIdx.x;
    if (e < E_CNT) {
        int d = load_edge(ei, e);
        int s = load_edge(ei, E_CNT + e);
        if ((unsigned)d < BN && (unsigned)s < BN) {
            int pos = atomicAdd(&g_cursor[d], 1);
            if (pos < E_CNT) g_bucket[pos] = s;
        }
    }
}

// ---------------- aggregation: one warp per node, MLP-boosted ----------------
// agg[i][c] = (deg>0) ? max_src(x_t[src][c]) - x_t[i][c] : 0
__global__ void agg_kernel() {
    int gtid = blockIdx.x * blockDim.x + threadIdx.x;
    int node = gtid >> 5;
    int lane = threadIdx.x & 31;
    if (node >= BN) return;
    int start = g_offs[node];
    int end   = g_offs[node + 1];
    int deg   = end - start;

    float m[6];
    #pragma unroll
    for (int j = 0; j < 6; ++j) m[j] = -CUDART_INF_F;

    // lane-parallel prefetch of neighbor ids (covers deg <= 32, typical ~16)
    int my_src = (lane < deg) ? g_bucket[start + lane] : 0;
    int cnt = deg < 32 ? deg : 32;

    int i = 0;
    for (; i + 2 <= cnt; i += 2) {       // unroll-by-2: 12 loads in flight
        int s0 = __shfl_sync(0xFFFFFFFFu, my_src, i);
        int s1 = __shfl_sync(0xFFFFFFFFu, my_src, i + 1);
        const float* x0 = g_xt + (size_t)s0 * C_IN;
        const float* x1 = g_xt + (size_t)s1 * C_IN;
        float v0[6], v1[6];
        #pragma unroll
        for (int j = 0; j < 6; ++j) v0[j] = x0[lane + 32 * j];
        #pragma unroll
        for (int j = 0; j < 6; ++j) v1[j] = x1[lane + 32 * j];
        #pragma unroll
        for (int j = 0; j < 6; ++j) m[j] = fmaxf(m[j], fmaxf(v0[j], v1[j]));
    }
    if (i < cnt) {
        int s0 = __shfl_sync(0xFFFFFFFFu, my_src, i);
        const float* x0 = g_xt + (size_t)s0 * C_IN;
        #pragma unroll
        for (int j = 0; j < 6; ++j) m[j] = fmaxf(m[j], x0[lane + 32 * j]);
    }
    // rare tail (deg > 32)
    for (int e = start + 32; e < end; ++e) {
        int s = g_bucket[e];
        const float* xs = g_xt + (size_t)s * C_IN;
        #pragma unroll
        for (int j = 0; j < 6; ++j) m[j] = fmaxf(m[j], xs[lane + 32 * j]);
    }

    const float* xi = g_xt + (size_t)node * C_IN;
    bool has = deg > 0;
    #pragma unroll
    for (int j = 0; j < 6; ++j) {
        float v = has ? (m[j] - xi[lane + 32 * j]) : 0.0f;
        __nv_bfloat16 hi, lo;
        split_bf16(v, hi, lo);
        size_t idx = (size_t)node * C_IN + lane + 32 * j;
        g_bg_hi[idx] = hi;
        g_bg_lo[idx] = lo;
    }
}

// ---------------- HMMA GEMM: out = relu(A @ B + bias) ----------------
// 3-term bf16 split: D = A_hi*B_hi + A_hi*B_lo + A_lo*B_hi (fp32 reg accum).
// CTA tile 128(M) x 128(N); 8 warps = 4(M) x 2(N), warp tile 32 x 64.
// 6 outer K-chunks of 64 bf16; each fills 4 smem tiles (A_hi,A_lo,B_hi,B_lo)
// once and runs all 3 terms from them. Dynamic smem: 4 x 18KB = 72KB.
// smem pitch 144B -> bank-conflict-free ldmatrix.

#define PITCH_B 144
#define TILE_BYTES (128 * PITCH_B)     // 18432
#define GEMM_SMEM (4 * TILE_BYTES)     // 73728

extern __shared__ __align__(16) char g_dsm[];

__global__ __launch_bounds__(256, 2) void hmma_gemm_kernel(
    const float* __restrict__ bias, float* __restrict__ out)
{
    char* Ah = g_dsm;
    char* Al = g_dsm + TILE_BYTES;
    char* Bh = g_dsm + 2 * TILE_BYTES;
    char* Bl = g_dsm + 3 * TILE_BYTES;

    int tid  = threadIdx.x;
    int wid  = tid >> 5;
    int lane = tid & 31;
    int wm   = wid & 3;        // warp row 0..3  -> m offset wm*32
    int wn   = wid >> 2;       // warp col 0..1  -> n offset wn*64
    int n0 = blockIdx.x * 128;
    int m0 = blockIdx.y * 128;
    int bb = blockIdx.z;

    uint32_t ah_base = smem_u32(Ah);
    uint32_t al_base = smem_u32(Al);
    uint32_t bh_base = smem_u32(Bh);
    uint32_t bl_base = smem_u32(Bl);

    int row_in = lane & 7;
    int sub    = lane >> 3;      // 0..3

    const char* bx_hi = (const char*)g_bx_hi;
    const char* bx_lo = (const char*)g_bx_lo;
    const char* bg_hi = (const char*)g_bg_hi;
    const char* bg_lo = (const char*)g_bg_lo;
    const char* a_hi  = (const char*)g_a_hi;
    const char* a_lo  = (const char*)g_a_lo;

    int node0 = bb * Nn + n0;

    float acc[2][8][4];
    #pragma unroll
    for (int i = 0; i < 2; ++i)
        #pragma unroll
        for (int j = 0; j < 8; ++j)
            #pragma unroll
            for (int r = 0; r < 4; ++r) acc[i][j][r] = 0.0f;

    for (int c6 = 0; c6 < 6; ++c6) {
        const char* bh_src = (c6 < 3) ? bx_hi : bg_hi;
        const char* bl_src = (c6 < 3) ? bx_lo : bg_lo;
        int kkA = c6 * 64;                 // A K-offset (bf16 elements)
        int kkB = (c6 % 3) * 64;           // B K-offset within its source

        // fill 4 tiles: each thread writes 4 granules per tile
        #pragma unroll
        for (int i = 0; i < 4; ++i) {
            int idx = tid + 256 * i;       // 0..1023
            int row = idx >> 3;
            int q   = idx & 7;
            size_t a_off = (size_t)(m0 + row) * (K2 * 2) + kkA * 2 + q * 16;
            size_t b_off = (size_t)(node0 + row) * (C_IN * 2) + kkB * 2 + q * 16;
            uint32_t so = row * PITCH_B + q * 16;
            *(uint4*)(Ah + so) = *(const uint4*)(a_hi + a_off);
            *(uint4*)(Al + so) = *(const uint4*)(a_lo + a_off);
            *(uint4*)(Bh + so) = *(const uint4*)(bh_src + b_off);
            *(uint4*)(Bl + so) = *(const uint4*)(bl_src + b_off);
        }
        __syncthreads();

        #pragma unroll
        for (int ks = 0; ks < 4; ++ks) {
            int k0 = ks * 16;
            uint32_t a_row_off  = (wm * 32 + row_in + (sub & 1) * 8) * PITCH_B
                                  + (k0 + (sub >> 1) * 8) * 2;
            uint32_t b_lane_off = (wn * 64 + (sub >> 1) * 8 + row_in) * PITCH_B
                                  + (k0 + (sub & 1) * 8) * 2;

            uint32_t ah[2][4], al[2][4];
            #pragma unroll
            for (int f = 0; f < 2; ++f)
                ldsm_x4(ah_base + a_row_off + f * 16 * PITCH_B,
                        ah[f][0], ah[f][1], ah[f][2], ah[f][3]);

            uint32_t bh[8][2];
            #pragma unroll
            for (int j = 0; j < 4; ++j) {
                uint32_t r0, r1, r2, r3;
                ldsm_x4(bh_base + b_lane_off + j * 16 * PITCH_B, r0, r1, r2, r3);
                bh[j * 2][0] = r0; bh[j * 2][1] = r1;
                bh[j * 2 + 1][0] = r2; bh[j * 2 + 1][1] = r3;
            }
            // hi * hi
            #pragma unroll
            for (int mi = 0; mi < 2; ++mi)
                #pragma unroll
                for (int nj = 0; nj < 8; ++nj)
                    mma_bf16(acc[mi][nj][0], acc[mi][nj][1], acc[mi][nj][2], acc[mi][nj][3],
                             ah[mi][0], ah[mi][1], ah[mi][2], ah[mi][3],
                             bh[nj][0], bh[nj][1]);
            // lo * hi
            #pragma unroll
            for (int f = 0; f < 2; ++f)
                ldsm_x4(al_base + a_row_off + f * 16 * PITCH_B,
                        al[f][0], al[f][1], al[f][2], al[f][3]);
            #pragma unroll
            for (int mi = 0; mi < 2; ++mi)
                #pragma unroll
                for (int nj = 0; nj < 8; ++nj)
                    mma_bf16(acc[mi][nj][0], acc[mi][nj][1], acc[mi][nj][2], acc[mi][nj][3],
                             al[mi][0], al[mi][1], al[mi][2], al[mi][3],
                             bh[nj][0], bh[nj][1]);
            // hi * lo (overwrite bh regs with bl)
            #pragma unroll
            for (int j = 0; j < 4; ++j) {
                uint32_t r0, r1, r2, r3;
                ldsm_x4(bl_base + b_lane_off + j * 16 * PITCH_B, r0, r1, r2, r3);
                bh[j * 2][0] = r0; bh[j * 2][1] = r1;
                bh[j * 2 + 1][0] = r2; bh[j * 2 + 1][1] = r3;
            }
            #pragma unroll
            for (int mi = 0; mi < 2; ++mi)
                #pragma unroll
                for (int nj = 0; nj < 8; ++nj)
                    mma_bf16(acc[mi][nj][0], acc[mi][nj][1], acc[mi][nj][2], acc[mi][nj][3],
                             ah[mi][0], ah[mi][1], ah[mi][2], ah[mi][3],
                             bh[nj][0], bh[nj][1]);
        }
        __syncthreads();
    }

    // epilogue: bias + relu
    int g  = lane >> 2;        // 0..7
    int tq = lane & 3;         // 0..3
    #pragma unroll
    for (int mi = 0; mi < 2; ++mi) {
        int r0 = m0 + wm * 32 + mi * 16 + g;
        int r1 = r0 + 8;
        float bv0 = bias[r0];
        float bv1 = bias[r1];
        float* o0 = out + ((size_t)bb * C_OUT + r0) * Nn + n0 + wn * 64 + tq * 2;
        float* o1 = out + ((size_t)bb * C_OUT + r1) * Nn + n0 + wn * 64 + tq * 2;
        #pragma unroll
        for (int nj = 0; nj < 8; ++nj) {
            float2 v0, v1;
            v0.x = fmaxf(acc[mi][nj][0] + bv0, 0.0f);
            v0.y = fmaxf(acc[mi][nj][1] + bv0, 0.0f);
            v1.x = fmaxf(acc[mi][nj][2] + bv1, 0.0f);
            v1.y = fmaxf(acc[mi][nj][3] + bv1, 0.0f);
            *(float2*)(o0 + nj * 8) = v0;
            *(float2*)(o1 + nj * 8) = v1;
        }
    }
}

// ---------------- launcher ----------------
extern "C" void kernel_launch(void* const* d_in, const int* in_sizes, int n_in,
                              void* d_out, int out_size) {
    const float* x  = (const float*)d_in[0];       // (4,192,4096,1)
    const void*  ei = (const void*)d_in[1];        // (2, 262144) int32 or int64
    const float* W  = (const float*)d_in[2];       // (384, 384)
    const float* bv = (const float*)d_in[3];       // (384,)
    float* out = (float*)d_out;                    // (4,384,4096,1)

    cudaFuncSetAttribute(hmma_gemm_kernel,
                         cudaFuncAttributeMaxDynamicSharedMemorySize, GEMM_SMEM);

    prep_kernel<<<641, 256>>>(ei, W);                                  // 1
    transpose_kernel<<<dim3(Nn / 32, C_IN / 32, Bz), dim3(32, 8)>>>(x); // 2
    hist_kernel<<<E_CNT / 256, 256>>>(ei);                             // 3
    scan_kernel<<<1, 1024>>>();                                        // 4
    scatter_kernel<<<E_CNT / 256, 256>>>(ei);                          // 5
    agg_kernel<<<(BN * 32) / 256, 256>>>();                            // 6  <- ncu -s 5
    hmma_gemm_kernel<<<dim3(Nn / 128, C_OUT / 128, Bz), 256, GEMM_SMEM>>>(bv, out); // 7
}

// round 7
// speedup vs baseline: 2.7546x; 1.3177x over previous
#include <cuda_runtime.h>
#include <cuda_bf16.h>
#include <math_constants.h>
#include <cstdint>

// Problem constants
#define Bz     4
#define C_IN   192
#define Nn     4096
#define BN     (Bz * Nn)          // 16384 nodes
#define E_CNT  262144             // edges
#define C_OUT  384
#define K2     (2 * C_IN)         // 384  (combined GEMM K)
#define CAP    64                 // per-node bucket capacity

// ---------------- scratch (static device globals; no allocation) ----------------
__device__ float g_xt[BN * C_IN];                           // node-major fp32 x (agg gather)
__device__ __align__(16) __nv_bfloat16 g_bx_hi[BN * C_IN];  // x  node-major bf16 hi
__device__ __align__(16) __nv_bfloat16 g_bx_lo[BN * C_IN];  // x  node-major bf16 lo
__device__ __align__(16) __nv_bfloat16 g_bg_hi[BN * C_IN];  // agg node-major bf16 hi
__device__ __align__(16) __nv_bfloat16 g_bg_lo[BN * C_IN];  // agg node-major bf16 lo
__device__ __align__(16) __nv_bfloat16 g_a_hi[C_OUT * K2];  // A=[Wx|Wg] K-major bf16 hi
__device__ __align__(16) __nv_bfloat16 g_a_lo[C_OUT * K2];  // A lo
__device__ int   g_cnt[BN];
__device__ int   g_bucket[BN * CAP];     // fixed-stride buckets (4 MB)
__device__ int   g_ovsrc[E_CNT];         // overflow spill (exactness guarantee)
__device__ int   g_ovdst[E_CNT];
__device__ int   g_ovcnt;
__device__ int   g_is64;                 // edge dtype flag (1 = int64, 0 = int32)

// ---------------- helpers ----------------
__device__ __forceinline__ uint32_t smem_u32(const void* p) {
    uint32_t a;
    asm("{ .reg .u64 t; cvta.to.shared.u64 t, %1; cvt.u32.u64 %0, t; }" : "=r"(a) : "l"(p));
    return a;
}

__device__ __forceinline__ void ldsm_x4(uint32_t addr, uint32_t& r0, uint32_t& r1,
                                        uint32_t& r2, uint32_t& r3) {
    asm volatile("ldmatrix.sync.aligned.m8n8.x4.shared.b16 {%0,%1,%2,%3}, [%4];"
                 : "=r"(r0), "=r"(r1), "=r"(r2), "=r"(r3) : "r"(addr));
}

__device__ __forceinline__ void mma_bf16(float& c0, float& c1, float& c2, float& c3,
                                         uint32_t a0, uint32_t a1, uint32_t a2, uint32_t a3,
                                         uint32_t b0, uint32_t b1) {
    asm volatile(
        "mma.sync.aligned.m16n8k16.row.col.f32.bf16.bf16.f32 "
        "{%0,%1,%2,%3}, {%4,%5,%6,%7}, {%8,%9}, {%0,%1,%2,%3};"
        : "+f"(c0), "+f"(c1), "+f"(c2), "+f"(c3)
        : "r"(a0), "r"(a1), "r"(a2), "r"(a3), "r"(b0), "r"(b1));
}

__device__ __forceinline__ int load_edge(const void* ei, int idx) {
    if (g_is64) return (int)((const long long*)ei)[idx];
    return ((const int*)ei)[idx];
}

__device__ __forceinline__ void split_bf16(float v, __nv_bfloat16& hi, __nv_bfloat16& lo) {
    hi = __float2bfloat16(v);
    lo = __float2bfloat16(v - __bfloat162float(hi));
}

// ---------------- merged prep: probe + zero counts + W deinterleave/split ------
// block 0           : edge-dtype probe (256 threads) + zero overflow counter
// blocks 1..64      : zero g_cnt
// blocks 65..640    : build A = [Wx | Wg] bf16 hi/lo
__global__ void prep_kernel(const void* __restrict__ ei, const float* __restrict__ W) {
    int blk = blockIdx.x;
    int t   = threadIdx.x;
    if (blk == 0) {
        if (t == 0) { g_is64 = 1; g_ovcnt = 0; }
        __threadfence();
        const long long* p = (const long long*)ei;
        long long v = p[t];
        if (v < 0 || v >= BN) atomicExch(&g_is64, 0);
    } else if (blk <= 64) {
        g_cnt[(blk - 1) * 256 + t] = 0;
    } else {
        int i = (blk - 65) * 256 + t;            // over C_OUT*K2
        int o = i / K2, k = i % K2;
        float v = (k < C_IN) ? W[o * K2 + 2 * k] : W[o * K2 + 2 * (k - C_IN) + 1];
        __nv_bfloat16 hi, lo;
        split_bf16(v, hi, lo);
        g_a_hi[i] = hi;
        g_a_lo[i] = lo;
    }
}

// x (B, C, N) -> node-major fp32 + bf16 hi/lo
__global__ void transpose_kernel(const float* __restrict__ x) {
    __shared__ float tile[32][33];
    int b  = blockIdx.z;
    int n0 = blockIdx.x * 32;
    int c0 = blockIdx.y * 32;
    int tx = threadIdx.x, ty = threadIdx.y;   // 32 x 8
    #pragma unroll
    for (int i = 0; i < 4; ++i) {
        int c = c0 + ty + 8 * i;
        tile[ty + 8 * i][tx] = x[((size_t)b * C_IN + c) * Nn + n0 + tx];
    }
    __syncthreads();
    #pragma unroll
    for (int i = 0; i < 4; ++i) {
        int n = n0 + ty + 8 * i;
        size_t idx = ((size_t)b * Nn + n) * C_IN + c0 + tx;
        float v = tile[tx][ty + 8 * i];
        g_xt[idx] = v;
        __nv_bfloat16 hi, lo;
        split_bf16(v, hi, lo);
        g_bx_hi[idx] = hi;
        g_bx_lo[idx] = lo;
    }
}

// ---------------- single-pass bucketing (no hist/scan) ----------------
__global__ void scatter_kernel(const void* __restrict__ ei) {
    int e = blockIdx.x * blockDim.x + threadIdx.x;
    if (e < E_CNT) {
        int d = load_edge(ei, e);
        int s = load_edge(ei, E_CNT + e);
        if ((unsigned)d < BN && (unsigned)s < BN) {
            int pos = atomicAdd(&g_cnt[d], 1);
            if (pos < CAP) {
                g_bucket[d * CAP + pos] = s;
            } else {                              // exact spill path (≈never)
                int op = atomicAdd(&g_ovcnt, 1);
                if (op < E_CNT) { g_ovsrc[op] = s; g_ovdst[op] = d; }
            }
        }
    }
}

// ---------------- aggregation: one warp per node ----------------
// agg[i][c] = (deg>0) ? max_src(x_t[src][c]) - x_t[i][c] : 0
__global__ void agg_kernel() {
    int gtid = blockIdx.x * blockDim.x + threadIdx.x;
    int node = gtid >> 5;
    int lane = threadIdx.x & 31;
    if (node >= BN) return;
    int deg = g_cnt[node];
    int nb  = deg < CAP ? deg : CAP;

    float m[6];
    #pragma unroll
    for (int j = 0; j < 6; ++j) m[j] = -CUDART_INF_F;

    // lane-parallel coalesced prefetch of neighbor ids (covers nb <= 32, typ ~16)
    const int* brow = g_bucket + node * CAP;
    int my_src = (lane < nb) ? brow[lane] : 0;
    int cnt = nb < 32 ? nb : 32;

    int i = 0;
    for (; i + 2 <= cnt; i += 2) {       // unroll-by-2: 12 loads in flight
        int s0 = __shfl_sync(0xFFFFFFFFu, my_src, i);
        int s1 = __shfl_sync(0xFFFFFFFFu, my_src, i + 1);
        const float* x0 = g_xt + (size_t)s0 * C_IN;
        const float* x1 = g_xt + (size_t)s1 * C_IN;
        float v0[6], v1[6];
        #pragma unroll
        for (int j = 0; j < 6; ++j) v0[j] = x0[lane + 32 * j];
        #pragma unroll
        for (int j = 0; j < 6; ++j) v1[j] = x1[lane + 32 * j];
        #pragma unroll
        for (int j = 0; j < 6; ++j) m[j] = fmaxf(m[j], fmaxf(v0[j], v1[j]));
    }
    if (i < cnt) {
        int s0 = __shfl_sync(0xFFFFFFFFu, my_src, i);
        const float* x0 = g_xt + (size_t)s0 * C_IN;
        #pragma unroll
        for (int j = 0; j < 6; ++j) m[j] = fmaxf(m[j], x0[lane + 32 * j]);
    }
    // rare tail (deg in (32, CAP])
    for (int e = 32; e < nb; ++e) {
        int s = brow[e];
        const float* xs = g_xt + (size_t)s * C_IN;
        #pragma unroll
        for (int j = 0; j < 6; ++j) m[j] = fmaxf(m[j], xs[lane + 32 * j]);
    }
    // exact overflow sweep (g_ovcnt == 0 in practice -> one broadcast load)
    int nov = g_ovcnt;
    if (nov > E_CNT) nov = E_CNT;
    for (int e = 0; e < nov; ++e) {
        if (g_ovdst[e] == node) {
            const float* xs = g_xt + (size_t)g_ovsrc[e] * C_IN;
            #pragma unroll
            for (int j = 0; j < 6; ++j) m[j] = fmaxf(m[j], xs[lane + 32 * j]);
        }
    }

    const float* xi = g_xt + (size_t)node * C_IN;
    bool has = deg > 0;
    #pragma unroll
    for (int j = 0; j < 6; ++j) {
        float v = has ? (m[j] - xi[lane + 32 * j]) : 0.0f;
        __nv_bfloat16 hi, lo;
        split_bf16(v, hi, lo);
        size_t idx = (size_t)node * C_IN + lane + 32 * j;
        g_bg_hi[idx] = hi;
        g_bg_lo[idx] = lo;
    }
}

// ---------------- HMMA GEMM: out = relu(A @ B + bias) ----------------
// 3-term bf16 split: D = A_hi*B_hi + A_hi*B_lo + A_lo*B_hi (fp32 reg accum).
// CTA tile 128(M) x 128(N); 8 warps = 4(M) x 2(N), warp tile 32 x 64.
// 6 outer K-chunks of 64 bf16; each fills 4 smem tiles (A_hi,A_lo,B_hi,B_lo)
// once and runs all 3 terms from them. Dynamic smem: 4 x 18KB = 72KB.
// smem pitch 144B -> bank-conflict-free ldmatrix.

#define PITCH_B 144
#define TILE_BYTES (128 * PITCH_B)     // 18432
#define GEMM_SMEM (4 * TILE_BYTES)     // 73728

extern __shared__ __align__(16) char g_dsm[];

__global__ __launch_bounds__(256, 2) void hmma_gemm_kernel(
    const float* __restrict__ bias, float* __restrict__ out)
{
    char* Ah = g_dsm;
    char* Al = g_dsm + TILE_BYTES;
    char* Bh = g_dsm + 2 * TILE_BYTES;
    char* Bl = g_dsm + 3 * TILE_BYTES;

    int tid  = threadIdx.x;
    int wid  = tid >> 5;
    int lane = tid & 31;
    int wm   = wid & 3;        // warp row 0..3  -> m offset wm*32
    int wn   = wid >> 2;       // warp col 0..1  -> n offset wn*64
    int n0 = blockIdx.x * 128;
    int m0 = blockIdx.y * 128;
    int bb = blockIdx.z;

    uint32_t ah_base = smem_u32(Ah);
    uint32_t al_base = smem_u32(Al);
    uint32_t bh_base = smem_u32(Bh);
    uint32_t bl_base = smem_u32(Bl);

    int row_in = lane & 7;
    int sub    = lane >> 3;      // 0..3

    const char* bx_hi = (const char*)g_bx_hi;
    const char* bx_lo = (const char*)g_bx_lo;
    const char* bg_hi = (const char*)g_bg_hi;
    const char* bg_lo = (const char*)g_bg_lo;
    const char* a_hi  = (const char*)g_a_hi;
    const char* a_lo  = (const char*)g_a_lo;

    int node0 = bb * Nn + n0;

    float acc[2][8][4];
    #pragma unroll
    for (int i = 0; i < 2; ++i)
        #pragma unroll
        for (int j = 0; j < 8; ++j)
            #pragma unroll
            for (int r = 0; r < 4; ++r) acc[i][j][r] = 0.0f;

    for (int c6 = 0; c6 < 6; ++c6) {
        const char* bh_src = (c6 < 3) ? bx_hi : bg_hi;
        const char* bl_src = (c6 < 3) ? bx_lo : bg_lo;
        int kkA = c6 * 64;                 // A K-offset (bf16 elements)
        int kkB = (c6 % 3) * 64;           // B K-offset within its source

        // fill 4 tiles: each thread writes 4 granules per tile
        #pragma unroll
        for (int i = 0; i < 4; ++i) {
            int idx = tid + 256 * i;       // 0..1023
            int row = idx >> 3;
            int q   = idx & 7;
            size_t a_off = (size_t)(m0 + row) * (K2 * 2) + kkA * 2 + q * 16;
            size_t b_off = (size_t)(node0 + row) * (C_IN * 2) + kkB * 2 + q * 16;
            uint32_t so = row * PITCH_B + q * 16;
            *(uint4*)(Ah + so) = *(const uint4*)(a_hi + a_off);
            *(uint4*)(Al + so) = *(const uint4*)(a_lo + a_off);
            *(uint4*)(Bh + so) = *(const uint4*)(bh_src + b_off);
            *(uint4*)(Bl + so) = *(const uint4*)(bl_src + b_off);
        }
        __syncthreads();

        #pragma unroll
        for (int ks = 0; ks < 4; ++ks) {
            int k0 = ks * 16;
            uint32_t a_row_off  = (wm * 32 + row_in + (sub & 1) * 8) * PITCH_B
                                  + (k0 + (sub >> 1) * 8) * 2;
            uint32_t b_lane_off = (wn * 64 + (sub >> 1) * 8 + row_in) * PITCH_B
                                  + (k0 + (sub & 1) * 8) * 2;

            uint32_t ah[2][4], al[2][4];
            #pragma unroll
            for (int f = 0; f < 2; ++f)
                ldsm_x4(ah_base + a_row_off + f * 16 * PITCH_B,
                        ah[f][0], ah[f][1], ah[f][2], ah[f][3]);

            uint32_t bh[8][2];
            #pragma unroll
            for (int j = 0; j < 4; ++j) {
                uint32_t r0, r1, r2, r3;
                ldsm_x4(bh_base + b_lane_off + j * 16 * PITCH_B, r0, r1, r2, r3);
                bh[j * 2][0] = r0; bh[j * 2][1] = r1;
                bh[j * 2 + 1][0] = r2; bh[j * 2 + 1][1] = r3;
            }
            // hi * hi
            #pragma unroll
            for (int mi = 0; mi < 2; ++mi)
                #pragma unroll
                for (int nj = 0; nj < 8; ++nj)
                    mma_bf16(acc[mi][nj][0], acc[mi][nj][1], acc[mi][nj][2], acc[mi][nj][3],
                             ah[mi][0], ah[mi][1], ah[mi][2], ah[mi][3],
                             bh[nj][0], bh[nj][1]);
            // lo * hi
            #pragma unroll
            for (int f = 0; f < 2; ++f)
                ldsm_x4(al_base + a_row_off + f * 16 * PITCH_B,
                        al[f][0], al[f][1], al[f][2], al[f][3]);
            #pragma unroll
            for (int mi = 0; mi < 2; ++mi)
                #pragma unroll
                for (int nj = 0; nj < 8; ++nj)
                    mma_bf16(acc[mi][nj][0], acc[mi][nj][1], acc[mi][nj][2], acc[mi][nj][3],
                             al[mi][0], al[mi][1], al[mi][2], al[mi][3],
                             bh[nj][0], bh[nj][1]);
            // hi * lo (overwrite bh regs with bl)
            #pragma unroll
            for (int j = 0; j < 4; ++j) {
                uint32_t r0, r1, r2, r3;
                ldsm_x4(bl_base + b_lane_off + j * 16 * PITCH_B, r0, r1, r2, r3);
                bh[j * 2][0] = r0; bh[j * 2][1] = r1;
                bh[j * 2 + 1][0] = r2; bh[j * 2 + 1][1] = r3;
            }
            #pragma unroll
            for (int mi = 0; mi < 2; ++mi)
                #pragma unroll
                for (int nj = 0; nj < 8; ++nj)
                    mma_bf16(acc[mi][nj][0], acc[mi][nj][1], acc[mi][nj][2], acc[mi][nj][3],
                             ah[mi][0], ah[mi][1], ah[mi][2], ah[mi][3],
                             bh[nj][0], bh[nj][1]);
        }
        __syncthreads();
    }

    // epilogue: bias + relu
    int g  = lane >> 2;        // 0..7
    int tq = lane & 3;         // 0..3
    #pragma unroll
    for (int mi = 0; mi < 2; ++mi) {
        int r0 = m0 + wm * 32 + mi * 16 + g;
        int r1 = r0 + 8;
        float bv0 = bias[r0];
        float bv1 = bias[r1];
        float* o0 = out + ((size_t)bb * C_OUT + r0) * Nn + n0 + wn * 64 + tq * 2;
        float* o1 = out + ((size_t)bb * C_OUT + r1) * Nn + n0 + wn * 64 + tq * 2;
        #pragma unroll
        for (int nj = 0; nj < 8; ++nj) {
            float2 v0, v1;
            v0.x = fmaxf(acc[mi][nj][0] + bv0, 0.0f);
            v0.y = fmaxf(acc[mi][nj][1] + bv0, 0.0f);
            v1.x = fmaxf(acc[mi][nj][2] + bv1, 0.0f);
            v1.y = fmaxf(acc[mi][nj][3] + bv1, 0.0f);
            *(float2*)(o0 + nj * 8) = v0;
            *(float2*)(o1 + nj * 8) = v1;
        }
    }
}

// ---------------- launcher ----------------
extern "C" void kernel_launch(void* const* d_in, const int* in_sizes, int n_in,
                              void* d_out, int out_size) {
    const float* x  = (const float*)d_in[0];       // (4,192,4096,1)
    const void*  ei = (const void*)d_in[1];        // (2, 262144) int32 or int64
    const float* W  = (const float*)d_in[2];       // (384, 384)
    const float* bv = (const float*)d_in[3];       // (384,)
    float* out = (float*)d_out;                    // (4,384,4096,1)

    cudaFuncSetAttribute(hmma_gemm_kernel,
                         cudaFuncAttributeMaxDynamicSharedMemorySize, GEMM_SMEM);

    prep_kernel<<<641, 256>>>(ei, W);                                   // 1
    transpose_kernel<<<dim3(Nn / 32, C_IN / 32, Bz), dim3(32, 8)>>>(x); // 2
    scatter_kernel<<<E_CNT / 256, 256>>>(ei);                           // 3
    agg_kernel<<<(BN * 32) / 256, 256>>>();                             // 4
    hmma_gemm_kernel<<<dim3(Nn / 128, C_OUT / 128, Bz), 256, GEMM_SMEM>>>(bv, out); // 5
}

// round 8
// speedup vs baseline: 2.9089x; 1.0560x over previous
#include <cuda_runtime.h>
#include <cuda_bf16.h>
#include <math_constants.h>
#include <cstdint>

// Problem constants
#define Bz     4
#define C_IN   192
#define Nn     4096
#define BN     (Bz * Nn)          // 16384 nodes
#define E_CNT  262144             // edges
#define C_OUT  384
#define K2     (2 * C_IN)         // 384  (combined GEMM K)
#define CAP    64                 // per-node bucket capacity

// ---------------- scratch (static device globals; no allocation) ----------------
__device__ __align__(16) float g_xt[BN * C_IN];             // node-major fp32 x (agg gather)
__device__ __align__(16) __nv_bfloat16 g_bx_hi[BN * C_IN];  // x  node-major bf16 hi
__device__ __align__(16) __nv_bfloat16 g_bx_lo[BN * C_IN];  // x  node-major bf16 lo
__device__ __align__(16) __nv_bfloat16 g_bg_hi[BN * C_IN];  // agg node-major bf16 hi
__device__ __align__(16) __nv_bfloat16 g_bg_lo[BN * C_IN];  // agg node-major bf16 lo
__device__ __align__(16) __nv_bfloat16 g_a_hi[C_OUT * K2];  // A=[Wx|Wg] K-major bf16 hi
__device__ __align__(16) __nv_bfloat16 g_a_lo[C_OUT * K2];  // A lo
__device__ int   g_cnt[BN];
__device__ int   g_bucket[BN * CAP];     // fixed-stride buckets (4 MB)
__device__ int   g_ovsrc[E_CNT];         // overflow spill (exactness guarantee)
__device__ int   g_ovdst[E_CNT];
__device__ int   g_ovcnt;
__device__ int   g_is64;                 // edge dtype flag (1 = int64, 0 = int32)

// ---------------- helpers ----------------
__device__ __forceinline__ uint32_t smem_u32(const void* p) {
    uint32_t a;
    asm("{ .reg .u64 t; cvta.to.shared.u64 t, %1; cvt.u32.u64 %0, t; }" : "=r"(a) : "l"(p));
    return a;
}

__device__ __forceinline__ void ldsm_x4(uint32_t addr, uint32_t& r0, uint32_t& r1,
                                        uint32_t& r2, uint32_t& r3) {
    asm volatile("ldmatrix.sync.aligned.m8n8.x4.shared.b16 {%0,%1,%2,%3}, [%4];"
                 : "=r"(r0), "=r"(r1), "=r"(r2), "=r"(r3) : "r"(addr));
}

__device__ __forceinline__ void mma_bf16(float& c0, float& c1, float& c2, float& c3,
                                         uint32_t a0, uint32_t a1, uint32_t a2, uint32_t a3,
                                         uint32_t b0, uint32_t b1) {
    asm volatile(
        "mma.sync.aligned.m16n8k16.row.col.f32.bf16.bf16.f32 "
        "{%0,%1,%2,%3}, {%4,%5,%6,%7}, {%8,%9}, {%0,%1,%2,%3};"
        : "+f"(c0), "+f"(c1), "+f"(c2), "+f"(c3)
        : "r"(a0), "r"(a1), "r"(a2), "r"(a3), "r"(b0), "r"(b1));
}

__device__ __forceinline__ int load_edge(const void* ei, int idx) {
    if (g_is64) return (int)((const long long*)ei)[idx];
    return ((const int*)ei)[idx];
}

__device__ __forceinline__ void split_bf16(float v, __nv_bfloat16& hi, __nv_bfloat16& lo) {
    hi = __float2bfloat16(v);
    lo = __float2bfloat16(v - __bfloat162float(hi));
}

__device__ __forceinline__ float4 max4(float4 a, float4 b) {
    float4 r;
    r.x = fmaxf(a.x, b.x); r.y = fmaxf(a.y, b.y);
    r.z = fmaxf(a.z, b.z); r.w = fmaxf(a.w, b.w);
    return r;
}

// split a float4 into packed-bf16 hi/lo uint2s
__device__ __forceinline__ void split4(float4 v, uint2& hi, uint2& lo) {
    __nv_bfloat16 h0, h1, h2, h3, l0, l1, l2, l3;
    split_bf16(v.x, h0, l0); split_bf16(v.y, h1, l1);
    split_bf16(v.z, h2, l2); split_bf16(v.w, h3, l3);
    hi.x = (uint32_t)*(uint16_t*)&h0 | ((uint32_t)*(uint16_t*)&h1 << 16);
    hi.y = (uint32_t)*(uint16_t*)&h2 | ((uint32_t)*(uint16_t*)&h3 << 16);
    lo.x = (uint32_t)*(uint16_t*)&l0 | ((uint32_t)*(uint16_t*)&l1 << 16);
    lo.y = (uint32_t)*(uint16_t*)&l2 | ((uint32_t)*(uint16_t*)&l3 << 16);
}

// ---------------- merged prep: probe + zero counts + W deinterleave/split ------
__global__ void prep_kernel(const void* __restrict__ ei, const float* __restrict__ W) {
    int blk = blockIdx.x;
    int t   = threadIdx.x;
    if (blk == 0) {
        if (t == 0) { g_is64 = 1; g_ovcnt = 0; }
        __threadfence();
        const long long* p = (const long long*)ei;
        long long v = p[t];
        if (v < 0 || v >= BN) atomicExch(&g_is64, 0);
    } else if (blk <= 64) {
        g_cnt[(blk - 1) * 256 + t] = 0;
    } else {
        int i = (blk - 65) * 256 + t;            // over C_OUT*K2
        int o = i / K2, k = i % K2;
        float v = (k < C_IN) ? W[o * K2 + 2 * k] : W[o * K2 + 2 * (k - C_IN) + 1];
        __nv_bfloat16 hi, lo;
        split_bf16(v, hi, lo);
        g_a_hi[i] = hi;
        g_a_lo[i] = lo;
    }
}

// ---------------- fused transpose + scatter ----------------
// blocks 0..1023    : edge scatter into fixed-capacity buckets
// blocks 1024..4095 : x (B,C,N) -> node-major fp32 + bf16 hi/lo (32x32 tiles)
__global__ void transpose_scatter_kernel(const float* __restrict__ x,
                                         const void* __restrict__ ei) {
    __shared__ float tile[32][33];
    int blk = blockIdx.x;
    int tid = threadIdx.x;

    if (blk < 1024) {
        int e = blk * 256 + tid;
        int d = load_edge(ei, e);
        int s = load_edge(ei, E_CNT + e);
        if ((unsigned)d < BN && (unsigned)s < BN) {
            int pos = atomicAdd(&g_cnt[d], 1);
            if (pos < CAP) {
                g_bucket[d * CAP + pos] = s;
            } else {                              // exact spill path (≈never)
                int op = atomicAdd(&g_ovcnt, 1);
                if (op < E_CNT) { g_ovsrc[op] = s; g_ovdst[op] = d; }
            }
        }
        return;
    }

    int q  = blk - 1024;                 // 0..3071
    int n0 = (q & 127) * 32;             // 128 n-tiles
    int c0 = ((q >> 7) % 6) * 32;        // 6 c-tiles
    int b  = q / (128 * 6);              // 4 batches
    int tx = tid & 31, ty = tid >> 5;    // 32 x 8
    #pragma unroll
    for (int i = 0; i < 4; ++i) {
        int c = c0 + ty + 8 * i;
        tile[ty + 8 * i][tx] = x[((size_t)b * C_IN + c) * Nn + n0 + tx];
    }
    __syncthreads();
    #pragma unroll
    for (int i = 0; i < 4; ++i) {
        int n = n0 + ty + 8 * i;
        size_t idx = ((size_t)b * Nn + n) * C_IN + c0 + tx;
        float v = tile[tx][ty + 8 * i];
        g_xt[idx] = v;
        __nv_bfloat16 hi, lo;
        split_bf16(v, hi, lo);
        g_bx_hi[idx] = hi;
        g_bx_lo[idx] = lo;
    }
}

// ---------------- aggregation: one warp per node, float4 gathers ----------------
// channel layout per warp: lane owns channels [4*lane, 4*lane+4); lanes 0..15
// additionally own [128 + 4*lane, 128 + 4*lane + 4).
__global__ void agg_kernel() {
    int gtid = blockIdx.x * blockDim.x + threadIdx.x;
    int node = gtid >> 5;
    int lane = threadIdx.x & 31;
    if (node >= BN) return;
    int deg = g_cnt[node];
    int nb  = deg < CAP ? deg : CAP;
    bool lo16 = lane < 16;

    const float4 NEG4 = make_float4(-CUDART_INF_F, -CUDART_INF_F, -CUDART_INF_F, -CUDART_INF_F);
    float4 ma = NEG4, mb = NEG4;

    // lane-parallel coalesced prefetch of neighbor ids
    const int* brow = g_bucket + node * CAP;
    int my_src = (lane < nb) ? brow[lane] : 0;
    int cnt = nb < 32 ? nb : 32;

    int i = 0;
    for (; i + 4 <= cnt; i += 4) {       // 4 neighbors in flight, float4-wide
        int s0 = __shfl_sync(0xFFFFFFFFu, my_src, i);
        int s1 = __shfl_sync(0xFFFFFFFFu, my_src, i + 1);
        int s2 = __shfl_sync(0xFFFFFFFFu, my_src, i + 2);
        int s3 = __shfl_sync(0xFFFFFFFFu, my_src, i + 3);
        const float4* r0 = (const float4*)(g_xt + (size_t)s0 * C_IN);
        const float4* r1 = (const float4*)(g_xt + (size_t)s1 * C_IN);
        const float4* r2 = (const float4*)(g_xt + (size_t)s2 * C_IN);
        const float4* r3 = (const float4*)(g_xt + (size_t)s3 * C_IN);
        float4 a0 = r0[lane], a1 = r1[lane], a2 = r2[lane], a3 = r3[lane];
        if (lo16) {
            float4 b0 = r0[32 + lane], b1 = r1[32 + lane];
            float4 b2 = r2[32 + lane], b3 = r3[32 + lane];
            mb = max4(mb, max4(max4(b0, b1), max4(b2, b3)));
        }
        ma = max4(ma, max4(max4(a0, a1), max4(a2, a3)));
    }
    for (; i < cnt; ++i) {
        int s0 = __shfl_sync(0xFFFFFFFFu, my_src, i);
        const float4* r0 = (const float4*)(g_xt + (size_t)s0 * C_IN);
        ma = max4(ma, r0[lane]);
        if (lo16) mb = max4(mb, r0[32 + lane]);
    }
    // rare tail (deg in (32, CAP]) — brow[e] is a uniform broadcast load
    for (int e = 32; e < nb; ++e) {
        int s = brow[e];
        const float4* r = (const float4*)(g_xt + (size_t)s * C_IN);
        ma = max4(ma, r[lane]);
        if (lo16) mb = max4(mb, r[32 + lane]);
    }
    // exact overflow sweep (g_ovcnt == 0 in practice)
    int nov = g_ovcnt;
    if (nov > E_CNT) nov = E_CNT;
    for (int e = 0; e < nov; ++e) {
        if (g_ovdst[e] == node) {
            const float4* r = (const float4*)(g_xt + (size_t)g_ovsrc[e] * C_IN);
            ma = max4(ma, r[lane]);
            if (lo16) mb = max4(mb, r[32 + lane]);
        }
    }

    const float4* xr = (const float4*)(g_xt + (size_t)node * C_IN);
    bool has = deg > 0;
    {
        float4 xa = xr[lane];
        float4 va = has ? make_float4(ma.x - xa.x, ma.y - xa.y, ma.z - xa.z, ma.w - xa.w)
                        : make_float4(0.f, 0.f, 0.f, 0.f);
        uint2 hi, lo;
        split4(va, hi, lo);
        size_t idx = (size_t)node * C_IN + lane * 4;
        *(uint2*)((char*)g_bg_hi + idx * 2) = hi;
        *(uint2*)((char*)g_bg_lo + idx * 2) = lo;
    }
    if (lo16) {
        float4 xb = xr[32 + lane];
        float4 vb = has ? make_float4(mb.x - xb.x, mb.y - xb.y, mb.z - xb.z, mb.w - xb.w)
                        : make_float4(0.f, 0.f, 0.f, 0.f);
        uint2 hi, lo;
        split4(vb, hi, lo);
        size_t idx = (size_t)node * C_IN + 128 + lane * 4;
        *(uint2*)((char*)g_bg_hi + idx * 2) = hi;
        *(uint2*)((char*)g_bg_lo + idx * 2) = lo;
    }
}

// ---------------- HMMA GEMM: out = relu(A @ B + bias) ----------------
// 3-term bf16 split: D = A_hi*B_hi + A_hi*B_lo + A_lo*B_hi (fp32 reg accum).
// CTA tile 128(M) x 128(N); 8 warps = 4(M) x 2(N), warp tile 32 x 64.
// 6 outer K-chunks of 64 bf16; each fills 4 smem tiles (A_hi,A_lo,B_hi,B_lo)
// once and runs all 3 terms from them. Dynamic smem: 4 x 18KB = 72KB.
// smem pitch 144B -> bank-conflict-free ldmatrix.

#define PITCH_B 144
#define TILE_BYTES (128 * PITCH_B)     // 18432
#define GEMM_SMEM (4 * TILE_BYTES)     // 73728

extern __shared__ __align__(16) char g_dsm[];

__global__ __launch_bounds__(256, 2) void hmma_gemm_kernel(
    const float* __restrict__ bias, float* __restrict__ out)
{
    char* Ah = g_dsm;
    char* Al = g_dsm + TILE_BYTES;
    char* Bh = g_dsm + 2 * TILE_BYTES;
    char* Bl = g_dsm + 3 * TILE_BYTES;

    int tid  = threadIdx.x;
    int wid  = tid >> 5;
    int lane = tid & 31;
    int wm   = wid & 3;        // warp row 0..3  -> m offset wm*32
    int wn   = wid >> 2;       // warp col 0..1  -> n offset wn*64
    int n0 = blockIdx.x * 128;
    int m0 = blockIdx.y * 128;
    int bb = blockIdx.z;

    uint32_t ah_base = smem_u32(Ah);
    uint32_t al_base = smem_u32(Al);
    uint32_t bh_base = smem_u32(Bh);
    uint32_t bl_base = smem_u32(Bl);

    int row_in = lane & 7;
    int sub    = lane >> 3;      // 0..3

    const char* bx_hi = (const char*)g_bx_hi;
    const char* bx_lo = (const char*)g_bx_lo;
    const char* bg_hi = (const char*)g_bg_hi;
    const char* bg_lo = (const char*)g_bg_lo;
    const char* a_hi  = (const char*)g_a_hi;
    const char* a_lo  = (const char*)g_a_lo;

    int node0 = bb * Nn + n0;

    float acc[2][8][4];
    #pragma unroll
    for (int i = 0; i < 2; ++i)
        #pragma unroll
        for (int j = 0; j < 8; ++j)
            #pragma unroll
            for (int r = 0; r < 4; ++r) acc[i][j][r] = 0.0f;

    for (int c6 = 0; c6 < 6; ++c6) {
        const char* bh_src = (c6 < 3) ? bx_hi : bg_hi;
        const char* bl_src = (c6 < 3) ? bx_lo : bg_lo;
        int kkA = c6 * 64;                 // A K-offset (bf16 elements)
        int kkB = (c6 % 3) * 64;           // B K-offset within its source

        // fill 4 tiles: each thread writes 4 granules per tile
        #pragma unroll
        for (int i = 0; i < 4; ++i) {
            int idx = tid + 256 * i;       // 0..1023
            int row = idx >> 3;
            int q   = idx & 7;
            size_t a_off = (size_t)(m0 + row) * (K2 * 2) + kkA * 2 + q * 16;
            size_t b_off = (size_t)(node0 + row) * (C_IN * 2) + kkB * 2 + q * 16;
            uint32_t so = row * PITCH_B + q * 16;
            *(uint4*)(Ah + so) = *(const uint4*)(a_hi + a_off);
            *(uint4*)(Al + so) = *(const uint4*)(a_lo + a_off);
            *(uint4*)(Bh + so) = *(const uint4*)(bh_src + b_off);
            *(uint4*)(Bl + so) = *(const uint4*)(bl_src + b_off);
        }
        __syncthreads();

        #pragma unroll
        for (int ks = 0; ks < 4; ++ks) {
            int k0 = ks * 16;
            uint32_t a_row_off  = (wm * 32 + row_in + (sub & 1) * 8) * PITCH_B
                                  + (k0 + (sub >> 1) * 8) * 2;
            uint32_t b_lane_off = (wn * 64 + (sub >> 1) * 8 + row_in) * PITCH_B
                                  + (k0 + (sub & 1) * 8) * 2;

            uint32_t ah[2][4], al[2][4];
            #pragma unroll
            for (int f = 0; f < 2; ++f)
                ldsm_x4(ah_base + a_row_off + f * 16 * PITCH_B,
                        ah[f][0], ah[f][1], ah[f][2], ah[f][3]);

            uint32_t bh[8][2];
            #pragma unroll
            for (int j = 0; j < 4; ++j) {
                uint32_t r0, r1, r2, r3;
                ldsm_x4(bh_base + b_lane_off + j * 16 * PITCH_B, r0, r1, r2, r3);
                bh[j * 2][0] = r0; bh[j * 2][1] = r1;
                bh[j * 2 + 1][0] = r2; bh[j * 2 + 1][1] = r3;
            }
            // hi * hi
            #pragma unroll
            for (int mi = 0; mi < 2; ++mi)
                #pragma unroll
                for (int nj = 0; nj < 8; ++nj)
                    mma_bf16(acc[mi][nj][0], acc[mi][nj][1], acc[mi][nj][2], acc[mi][nj][3],
                             ah[mi][0], ah[mi][1], ah[mi][2], ah[mi][3],
                             bh[nj][0], bh[nj][1]);
            // lo * hi
            #pragma unroll
            for (int f = 0; f < 2; ++f)
                ldsm_x4(al_base + a_row_off + f * 16 * PITCH_B,
                        al[f][0], al[f][1], al[f][2], al[f][3]);
            #pragma unroll
            for (int mi = 0; mi < 2; ++mi)
                #pragma unroll
                for (int nj = 0; nj < 8; ++nj)
                    mma_bf16(acc[mi][nj][0], acc[mi][nj][1], acc[mi][nj][2], acc[mi][nj][3],
                             al[mi][0], al[mi][1], al[mi][2], al[mi][3],
                             bh[nj][0], bh[nj][1]);
            // hi * lo (overwrite bh regs with bl)
            #pragma unroll
            for (int j = 0; j < 4; ++j) {
                uint32_t r0, r1, r2, r3;
                ldsm_x4(bl_base + b_lane_off + j * 16 * PITCH_B, r0, r1, r2, r3);
                bh[j * 2][0] = r0; bh[j * 2][1] = r1;
                bh[j * 2 + 1][0] = r2; bh[j * 2 + 1][1] = r3;
            }
            #pragma unroll
            for (int mi = 0; mi < 2; ++mi)
                #pragma unroll
                for (int nj = 0; nj < 8; ++nj)
                    mma_bf16(acc[mi][nj][0], acc[mi][nj][1], acc[mi][nj][2], acc[mi][nj][3],
                             ah[mi][0], ah[mi][1], ah[mi][2], ah[mi][3],
                             bh[nj][0], bh[nj][1]);
        }
        __syncthreads();
    }

    // epilogue: bias + relu
    int g  = lane >> 2;        // 0..7
    int tq = lane & 3;         // 0..3
    #pragma unroll
    for (int mi = 0; mi < 2; ++mi) {
        int r0 = m0 + wm * 32 + mi * 16 + g;
        int r1 = r0 + 8;
        float bv0 = bias[r0];
        float bv1 = bias[r1];
        float* o0 = out + ((size_t)bb * C_OUT + r0) * Nn + n0 + wn * 64 + tq * 2;
        float* o1 = out + ((size_t)bb * C_OUT + r1) * Nn + n0 + wn * 64 + tq * 2;
        #pragma unroll
        for (int nj = 0; nj < 8; ++nj) {
            float2 v0, v1;
            v0.x = fmaxf(acc[mi][nj][0] + bv0, 0.0f);
            v0.y = fmaxf(acc[mi][nj][1] + bv0, 0.0f);
            v1.x = fmaxf(acc[mi][nj][2] + bv1, 0.0f);
            v1.y = fmaxf(acc[mi][nj][3] + bv1, 0.0f);
            *(float2*)(o0 + nj * 8) = v0;
            *(float2*)(o1 + nj * 8) = v1;
        }
    }
}

// ---------------- launcher ----------------
extern "C" void kernel_launch(void* const* d_in, const int* in_sizes, int n_in,
                              void* d_out, int out_size) {
    const float* x  = (const float*)d_in[0];       // (4,192,4096,1)
    const void*  ei = (const void*)d_in[1];        // (2, 262144) int32 or int64
    const float* W  = (const float*)d_in[2];       // (384, 384)
    const float* bv = (const float*)d_in[3];       // (384,)
    float* out = (float*)d_out;                    // (4,384,4096,1)

    cudaFuncSetAttribute(hmma_gemm_kernel,
                         cudaFuncAttributeMaxDynamicSharedMemorySize, GEMM_SMEM);

    prep_kernel<<<641, 256>>>(ei, W);                                   // 1
    transpose_scatter_kernel<<<4096, 256>>>(x, ei);                     // 2
    agg_kernel<<<(BN * 32) / 256, 256>>>();                             // 3
    hmma_gemm_kernel<<<dim3(Nn / 128, C_OUT / 128, Bz), 256, GEMM_SMEM>>>(bv, out); // 4  <- profiled
}